// round 8
// baseline (speedup 1.0000x reference)
#include <cuda_runtime.h>
#include <cstdint>

#define NLAT 8192
#define NSMP 2048
#define ES 64
#define EA 32
#define FARK 64
#define TPB 256
#define FLT_BIG 3.402823466e+38f

#define ITEM_L 32
#define NITEMS (NLAT / ITEM_L)        // 256 items per lane
#define SLANES 8
#define ALANES 8
#define SBPL 25                        // state blocks per lane
#define ABPL 12                        // action blocks per lane
#define SBLKS (SLANES * SBPL)          // 200
#define NBLK  (SBLKS + ALANES * ABPL)  // 296 = one full wave at occ 2

// ---------------- scratch (device globals; no allocation) ------------------
__device__ int   g_ctr[16];                    // per-lane steal counters (reset by combine)
__device__ float g_part_s[SBLKS * 256 * 4];    // [block][sample_in_lane][4]
__device__ float g_part_a[ALANES * ABPL * 256 * 4];
__device__ float g_size_part[256];
__device__ float g_tail[2][NSMP];
__device__ float g_sq[2][NSMP];
__device__ int   g_cnt[2][NSMP];

__device__ __forceinline__ void ins4(float d, float& m0, float& m1, float& m2, float& m3) {
    float lo, hi;
    lo = fminf(m0, d);  hi = fmaxf(m0, d);  m0 = lo;
    lo = fminf(m1, hi); hi = fmaxf(m1, hi); m1 = lo;
    lo = fminf(m2, hi); hi = fmaxf(m2, hi); m2 = lo;
    m3 = fminf(m3, hi);
}
__device__ __forceinline__ void cpasync16(uint32_t s, const void* g) {
    asm volatile("cp.async.cg.shared.global [%0], [%1], 16;" :: "r"(s), "l"(g));
}
__device__ __forceinline__ void cp_commit() { asm volatile("cp.async.commit_group;"); }
__device__ __forceinline__ void cp_wait0()  { asm volatile("cp.async.wait_group 0;" ::: "memory"); }

// ---- per-lane stealing cov body; E = embedding dim ------------------------
// Work items are ITEM_L-latent chunks stolen off a per-lane atomic counter.
// Each block emits ONE partial top-4 per sample; merging partial min-4s over
// any partition of a fixed multiset gives the exact global min-4 -> the
// per-replay assignment variation cannot change the result (determinism ok).
template<int E>
__device__ void cov_lane(const float* __restrict__ smp, const float* __restrict__ lat,
                         int lane, int cidx, float* __restrict__ out4,
                         float* buf0, float* buf1, int* s_it) {
    const int tid = threadIdx.x;
    // sample row * 0.5 -> registers (exact rescale for FFMA-imm trick)
    float qh[E];
    {
        const float* q = smp + (size_t)(lane * 256 + tid) * E;
        #pragma unroll
        for (int k = 0; k < E; k += 4) {
            float4 v = *(const float4*)(q + k);
            qh[k] = 0.5f * v.x; qh[k+1] = 0.5f * v.y; qh[k+2] = 0.5f * v.z; qh[k+3] = 0.5f * v.w;
        }
    }
    float m0 = FLT_BIG, m1 = FLT_BIG, m2 = FLT_BIG, m3 = FLT_BIG;

    constexpr int ITEM_F4 = ITEM_L * E / 4;    // float4s per item
    if (tid == 0) s_it[0] = atomicAdd(&g_ctr[cidx], 1);
    __syncthreads();
    int it = s_it[0];
    float* cbuf = buf0;       // compute buffer
    float* pbuf = buf1;       // prefetch buffer
    int cur = 0;
    if (it < NITEMS) {
        const float4* src = (const float4*)(lat + (size_t)it * (ITEM_L * E));
        #pragma unroll
        for (int i = tid; i < ITEM_F4; i += TPB)
            cpasync16((uint32_t)__cvta_generic_to_shared(cbuf + i * 4), src + i);
    }
    cp_commit();

    while (it < NITEMS) {
        if (tid == 0) s_it[cur ^ 1] = atomicAdd(&g_ctr[cidx], 1);
        cp_wait0();               // only the compute buffer's group is outstanding here
        __syncthreads();
        const int nit = s_it[cur ^ 1];
        if (nit < NITEMS) {
            const float4* src = (const float4*)(lat + (size_t)nit * (ITEM_L * E));
            #pragma unroll
            for (int i = tid; i < ITEM_F4; i += TPB)
                cpasync16((uint32_t)__cvta_generic_to_shared(pbuf + i * 4), src + i);
        }
        cp_commit();

        const float4* tf = (const float4*)cbuf;
        #pragma unroll 1
        for (int p = 0; p < ITEM_L / 2; p++) {
            const float4* lrA = tf + (2 * p) * (E / 4);
            const float4* lrB = lrA + (E / 4);
            float a0 = 0.f, a1 = 0.f, a2 = 0.f, a3 = 0.f;
            float b0 = 0.f, b1 = 0.f, b2 = 0.f, b3 = 0.f;
            #pragma unroll
            for (int k = 0; k < E / 4; k++) {
                float4 va = lrA[k];
                float d0 = fmaf(va.x, -0.5f, qh[4*k]);
                float d1 = fmaf(va.y, -0.5f, qh[4*k+1]);
                float d2 = fmaf(va.z, -0.5f, qh[4*k+2]);
                float d3 = fmaf(va.w, -0.5f, qh[4*k+3]);
                a0 = fmaf(fabsf(d0), 2.0f, a0);
                a1 = fmaf(fabsf(d1), 2.0f, a1);
                a2 = fmaf(fabsf(d2), 2.0f, a2);
                a3 = fmaf(fabsf(d3), 2.0f, a3);
                float4 vb = lrB[k];
                float e0 = fmaf(vb.x, -0.5f, qh[4*k]);
                float e1 = fmaf(vb.y, -0.5f, qh[4*k+1]);
                float e2 = fmaf(vb.z, -0.5f, qh[4*k+2]);
                float e3 = fmaf(vb.w, -0.5f, qh[4*k+3]);
                b0 = fmaf(fabsf(e0), 2.0f, b0);
                b1 = fmaf(fabsf(e1), 2.0f, b1);
                b2 = fmaf(fabsf(e2), 2.0f, b2);
                b3 = fmaf(fabsf(e3), 2.0f, b3);
            }
            ins4((a0 + a1) + (a2 + a3), m0, m1, m2, m3);
            ins4((b0 + b1) + (b2 + b3), m0, m1, m2, m3);
        }
        float* t = cbuf; cbuf = pbuf; pbuf = t;
        cur ^= 1;
        it = nit;
    }
    *(float4*)(out4 + (size_t)tid * 4) = make_float4(m0, m1, m2, m3);
}

// ---- fused size-loss + coverage kernel, one wave of 296 blocks ------------
__global__ void __launch_bounds__(TPB, 2)
cov_kernel(const float* __restrict__ smp_s, const float* __restrict__ lat_s,
           const float* __restrict__ smp_a, const float* __restrict__ lat_a) {
    __shared__ __align__(16) float tile[2][ITEM_L * ES];   // 2 x 8 KB
    __shared__ float red[64];
    __shared__ int s_it[2];
    const int tid = threadIdx.x;
    const int bid = blockIdx.x;

    // size-loss prologue on 256 blocks: 64 rows each
    if (bid < 256) {
        if (tid < 64) {
            float a0 = 0.f, a1 = 0.f, a2 = 0.f, a3 = 0.f;
            if (bid < 128) {
                const float* row = lat_s + (size_t)(bid * 64 + tid) * ES;
                #pragma unroll
                for (int k = 0; k < ES; k += 4) {
                    float4 v = *(const float4*)(row + k);
                    a0 += fabsf(v.x); a1 += fabsf(v.y); a2 += fabsf(v.z); a3 += fabsf(v.w);
                }
            } else {
                const float* row = lat_a + (size_t)((bid - 128) * 64 + tid) * EA;
                #pragma unroll
                for (int k = 0; k < EA; k += 4) {
                    float4 v = *(const float4*)(row + k);
                    a0 += fabsf(v.x); a1 += fabsf(v.y); a2 += fabsf(v.z); a3 += fabsf(v.w);
                }
            }
            float n = (a0 + a1) + (a2 + a3);
            float viol = fmaxf(n - 1.0f, 0.0f);
            red[tid] = viol * viol;
        }
        __syncthreads();
        if (tid == 0) {
            float s = 0.f;
            #pragma unroll 8
            for (int i = 0; i < 64; i++) s += red[i];
            g_size_part[bid] = s;
        }
        __syncthreads();
    }

    if (bid < SBLKS) {
        const int lane = bid / SBPL;
        cov_lane<ES>(smp_s, lat_s, lane, lane,
                     g_part_s + (size_t)bid * 256 * 4, tile[0], tile[1], s_it);
    } else {
        const int ab = bid - SBLKS;
        const int lane = ab / ABPL;
        cov_lane<EA>(smp_a, lat_a, lane, 8 + lane,
                     g_part_a + (size_t)ab * 256 * 4, tile[0], tile[1], s_it);
    }
}

// ---- merge per-block partial top-4 -> tail/sq per sample ------------------
// grid (NSMP/TPB, 2): 1 thread per sample
__global__ void cov_merge_kernel() {
    const int sel = blockIdx.y;
    const int s   = blockIdx.x * TPB + threadIdx.x;
    const int lane = s >> 8, idx = s & 255;
    const int nb = sel ? ABPL : SBPL;
    const float* base = sel ? (g_part_a + (size_t)(lane * ABPL) * 256 * 4)
                            : (g_part_s + (size_t)(lane * SBPL) * 256 * 4);
    float m0 = FLT_BIG, m1 = FLT_BIG, m2 = FLT_BIG, m3 = FLT_BIG;
    for (int k = 0; k < nb; k++) {
        float4 v = *(const float4*)(base + ((size_t)k * 256 + idx) * 4);
        ins4(v.x, m0, m1, m2, m3);
        ins4(v.y, m0, m1, m2, m3);
        ins4(v.z, m0, m1, m2, m3);
        ins4(v.w, m0, m1, m2, m3);
    }
    g_tail[sel][s] = 0.25f * ((m0 + m1) + (m2 + m3));
    g_sq[sel][s]   = (m0 * m0 + m1 * m1) + (m2 * m2 + m3 * m3);
    g_cnt[sel][s]  = 0;
}

// ---- rank counts (stable ties == lax.top_k) -------------------------------
// grid (NSMP/TPB, 2, 16)
__global__ void rank_kernel() {
    __shared__ __align__(16) float tj_s[128];
    const int sel = blockIdx.y, tid = threadIdx.x;
    const int jbase = blockIdx.z * 128;
    if (tid < 128) tj_s[tid] = g_tail[sel][jbase + tid];
    __syncthreads();
    const int i  = blockIdx.x * TPB + tid;
    const int ti = __float_as_int(g_tail[sel][i]);   // positive floats: int order == fp order
    int cnt = 0;
    #pragma unroll
    for (int jj = 0; jj < 128; jj += 4) {
        float4 v = *(const float4*)(tj_s + jj);
        cnt += (__float_as_int(v.x) > ti) || (__float_as_int(v.x) == ti && (jbase + jj)     < i);
        cnt += (__float_as_int(v.y) > ti) || (__float_as_int(v.y) == ti && (jbase + jj + 1) < i);
        cnt += (__float_as_int(v.z) > ti) || (__float_as_int(v.z) == ti && (jbase + jj + 2) < i);
        cnt += (__float_as_int(v.w) > ti) || (__float_as_int(v.w) == ti && (jbase + jj + 3) < i);
    }
    if (cnt) atomicAdd(&g_cnt[sel][i], cnt);
}

// ---- final combine: deterministic fixed-order; also resets steal counters -
__global__ void combine_kernel(float* __restrict__ out) {
    __shared__ float red[8];
    const int tid = threadIdx.x;
    float acc = 0.0f;
    #pragma unroll
    for (int r = 0; r < NSMP / TPB; r++) {           // 8 independent loads in flight
        int i = r * TPB + tid;
        float v0 = (g_cnt[0][i] < FARK) ? g_sq[0][i] : 0.0f;
        float v1 = (g_cnt[1][i] < FARK) ? g_sq[1][i] : 0.0f;
        acc += v0 + v1;
    }
    #pragma unroll
    for (int off = 16; off; off >>= 1) acc += __shfl_down_sync(0xffffffffu, acc, off);
    if ((tid & 31) == 0) red[tid >> 5] = acc;
    __syncthreads();
    if (tid < 16) g_ctr[tid] = 0;                    // reset steal counters for next replay
    if (tid == 0) {
        float r8 = 0.f;
        #pragma unroll
        for (int w = 0; w < 8; w++) r8 += red[w];
        float ss = 0.f, sa = 0.f;
        #pragma unroll 4
        for (int b = 0; b < 128; b++)   ss += g_size_part[b];
        #pragma unroll 4
        for (int b = 128; b < 256; b++) sa += g_size_part[b];
        out[0] = ss / (float)NLAT + sa / (float)NLAT + r8 / (float)(FARK * 4);
    }
}

// ---------------- launch ----------------------------------------------------
extern "C" void kernel_launch(void* const* d_in, const int* in_sizes, int n_in,
                              void* d_out, int out_size) {
    const float* lat_s = (const float*)d_in[0];
    const float* lat_a = (const float*)d_in[1];
    const float* smp_s = (const float*)d_in[2];
    const float* smp_a = (const float*)d_in[3];
    float* out = (float*)d_out;

    cov_kernel<<<NBLK, TPB>>>(smp_s, lat_s, smp_a, lat_a);
    cov_merge_kernel<<<dim3(NSMP / TPB, 2), TPB>>>();
    rank_kernel<<<dim3(NSMP / TPB, 2, 16), TPB>>>();
    combine_kernel<<<1, TPB>>>(out);
}